// round 1
// baseline (speedup 1.0000x reference)
#include <cuda_runtime.h>
#include <cuda_bf16.h>
#include <cstdint>
#include <math.h>

// Problem constants
#define T_TOK 8192
#define DDIM  1024
#define FDIM  4096
#define NE    8
#define TOPK  2
#define NROWS (T_TOK * TOPK)      // 16384 (token, expert-slot) rows
#define MAXTILES 144              // sum ceil(n_e/128) <= 16384/128 + 7 = 135

// ---------------- static device scratch (no allocations allowed) ----------------
__device__ float d_act[(size_t)NROWS * FDIM];   // 256 MB: silu(gate)*up per row
__device__ float d_hbuf[(size_t)NROWS * DDIM];  // 64 MB: weighted down-proj per row
__device__ int   d_row_token[NROWS];
__device__ float d_row_w[NROWS];
__device__ int   d_token_rows[T_TOK * TOPK];
__device__ int   d_counts[NE];
__device__ int   d_offs[NE];
__device__ int   d_curs[NE];
__device__ int   d_tile_e[MAXTILES];
__device__ int   d_tile_m0[MAXTILES];
__device__ int   d_tile_end[MAXTILES];
__device__ int   d_ntiles;
__device__ int   d_topk_e[T_TOK * TOPK];
__device__ float d_topk_w[T_TOK * TOPK];

// ---------------- kernel 1: zero per-launch state ----------------
__global__ void init_kernel() {
    int i = threadIdx.x;
    if (i < NE) { d_counts[i] = 0; d_curs[i] = 0; }
}

// ---------------- kernel 2: router logits + softmax + top2 ----------------
// one block per token, 256 threads (8 warps = 8 experts)
__global__ void __launch_bounds__(256) router_kernel(
    const float* __restrict__ x, const float* __restrict__ rw, float* __restrict__ out)
{
    __shared__ float xs[DDIM];
    __shared__ float logits[NE];
    const int t = blockIdx.x;
    const int tid = threadIdx.x;

    // load token row (1024 floats) via float4, fully coalesced
    ((float4*)xs)[tid] = ((const float4*)(x + (size_t)t * DDIM))[tid];
    __syncthreads();

    const int w = tid >> 5, lane = tid & 31;
    const float* r = rw + (size_t)w * DDIM;
    float s = 0.f;
    #pragma unroll 8
    for (int i = lane; i < DDIM; i += 32) s += xs[i] * r[i];
    #pragma unroll
    for (int o = 16; o; o >>= 1) s += __shfl_down_sync(0xffffffffu, s, o);
    if (lane == 0) logits[w] = s;
    __syncthreads();

    if (tid == 0) {
        float l[NE], mx = -1e30f;
        #pragma unroll
        for (int e = 0; e < NE; e++) { l[e] = logits[e]; mx = fmaxf(mx, l[e]); }
        // write raw router logits (second output region)
        float* lo = out + (size_t)T_TOK * DDIM + (size_t)t * NE;
        #pragma unroll
        for (int e = 0; e < NE; e++) lo[e] = l[e];
        float p[NE], sum = 0.f;
        #pragma unroll
        for (int e = 0; e < NE; e++) { p[e] = expf(l[e] - mx); sum += p[e]; }
        float inv = 1.f / sum;
        #pragma unroll
        for (int e = 0; e < NE; e++) p[e] *= inv;
        // top-2, first index wins ties (jax top_k semantics)
        int i1 = 0; float p1 = p[0];
        #pragma unroll
        for (int e = 1; e < NE; e++) if (p[e] > p1) { p1 = p[e]; i1 = e; }
        int i2 = -1; float p2 = -1.f;
        #pragma unroll
        for (int e = 0; e < NE; e++) if (e != i1 && p[e] > p2) { p2 = p[e]; i2 = e; }
        d_topk_e[t * 2 + 0] = i1; d_topk_w[t * 2 + 0] = p1;
        d_topk_e[t * 2 + 1] = i2; d_topk_w[t * 2 + 1] = p2;
        atomicAdd(&d_counts[i1], 1);
        atomicAdd(&d_counts[i2], 1);
    }
}

// ---------------- kernel 3: prefix offsets + M-tile table ----------------
__global__ void offsets_kernel() {
    if (threadIdx.x != 0 || blockIdx.x != 0) return;
    int off = 0;
    for (int e = 0; e < NE; e++) { d_offs[e] = off; off += d_counts[e]; }
    int nt = 0;
    for (int e = 0; e < NE; e++) {
        int start = d_offs[e], cnt = d_counts[e];
        for (int i = 0; i < cnt; i += 128) {
            d_tile_e[nt] = e; d_tile_m0[nt] = start + i; d_tile_end[nt] = start + cnt;
            nt++;
        }
    }
    d_ntiles = nt;
}

// ---------------- kernel 4: scatter tokens into expert-grouped rows ----------------
__global__ void scatter_kernel() {
    int t = blockIdx.x * blockDim.x + threadIdx.x;
    if (t >= T_TOK) return;
    #pragma unroll
    for (int slot = 0; slot < TOPK; slot++) {
        int e = d_topk_e[t * 2 + slot];
        int pos = atomicAdd(&d_curs[e], 1);
        int r = d_offs[e] + pos;
        d_row_token[r] = t;
        d_row_w[r] = d_topk_w[t * 2 + slot];
        d_token_rows[t * 2 + slot] = r;
    }
}

// ---------------- kernel 5: GEMM1  act = silu(x@gateW^T) * (x@upW^T) ----------------
// M-tile 128 (rows from tile table), N-tile 128 (f), K-chunk 16, 256 threads, 8x8x2 per thread
__global__ void __launch_bounds__(256) gemm1_kernel(
    const float* __restrict__ x, const float* __restrict__ gw, const float* __restrict__ uw)
{
    const int tile = blockIdx.y;
    if (tile >= d_ntiles) return;
    const int e = d_tile_e[tile], m0 = d_tile_m0[tile], mend = d_tile_end[tile];
    const int n0 = blockIdx.x * 128;

    const float* Bg = gw + (size_t)e * FDIM * DDIM;
    const float* Bu = uw + (size_t)e * FDIM * DDIM;

    __shared__ float As[16][128];
    __shared__ float Bgs[16][128];
    __shared__ float Bus[16][128];

    const int tid = threadIdx.x;
    const int lrow = tid >> 1;           // 0..127: tile row for loading
    const int kq = (tid & 1) * 8;        // 0 or 8 within K-chunk

    int grow = m0 + lrow;
    int tok = d_row_token[grow < NROWS ? grow : (NROWS - 1)];
    const float* xrow  = x  + (size_t)tok * DDIM;
    const float* bgrow = Bg + (size_t)(n0 + lrow) * DDIM;
    const float* burow = Bu + (size_t)(n0 + lrow) * DDIM;

    const int tx = tid & 15, ty = tid >> 4;   // 16x16 thread grid

    float accg[8][8], accu[8][8];
    #pragma unroll
    for (int i = 0; i < 8; i++)
        #pragma unroll
        for (int j = 0; j < 8; j++) { accg[i][j] = 0.f; accu[i][j] = 0.f; }

    for (int kc = 0; kc < DDIM; kc += 16) {
        float4 a0 = *(const float4*)(xrow  + kc + kq);
        float4 a1 = *(const float4*)(xrow  + kc + kq + 4);
        float4 g0 = *(const float4*)(bgrow + kc + kq);
        float4 g1 = *(const float4*)(bgrow + kc + kq + 4);
        float4 u0 = *(const float4*)(burow + kc + kq);
        float4 u1 = *(const float4*)(burow + kc + kq + 4);
        As[kq + 0][lrow] = a0.x; As[kq + 1][lrow] = a0.y; As[kq + 2][lrow] = a0.z; As[kq + 3][lrow] = a0.w;
        As[kq + 4][lrow] = a1.x; As[kq + 5][lrow] = a1.y; As[kq + 6][lrow] = a1.z; As[kq + 7][lrow] = a1.w;
        Bgs[kq + 0][lrow] = g0.x; Bgs[kq + 1][lrow] = g0.y; Bgs[kq + 2][lrow] = g0.z; Bgs[kq + 3][lrow] = g0.w;
        Bgs[kq + 4][lrow] = g1.x; Bgs[kq + 5][lrow] = g1.y; Bgs[kq + 6][lrow] = g1.z; Bgs[kq + 7][lrow] = g1.w;
        Bus[kq + 0][lrow] = u0.x; Bus[kq + 1][lrow] = u0.y; Bus[kq + 2][lrow] = u0.z; Bus[kq + 3][lrow] = u0.w;
        Bus[kq + 4][lrow] = u1.x; Bus[kq + 5][lrow] = u1.y; Bus[kq + 6][lrow] = u1.z; Bus[kq + 7][lrow] = u1.w;
        __syncthreads();
        #pragma unroll
        for (int k = 0; k < 16; k++) {
            float a[8], bg[8], bu[8];
            *(float4*)(a)      = *(const float4*)&As[k][ty * 8];
            *(float4*)(a + 4)  = *(const float4*)&As[k][ty * 8 + 4];
            *(float4*)(bg)     = *(const float4*)&Bgs[k][tx * 8];
            *(float4*)(bg + 4) = *(const float4*)&Bgs[k][tx * 8 + 4];
            *(float4*)(bu)     = *(const float4*)&Bus[k][tx * 8];
            *(float4*)(bu + 4) = *(const float4*)&Bus[k][tx * 8 + 4];
            #pragma unroll
            for (int i = 0; i < 8; i++)
                #pragma unroll
                for (int j = 0; j < 8; j++) {
                    accg[i][j] += a[i] * bg[j];
                    accu[i][j] += a[i] * bu[j];
                }
        }
        __syncthreads();
    }

    // epilogue: act = silu(g) * u
    #pragma unroll
    for (int i = 0; i < 8; i++) {
        int row = m0 + ty * 8 + i;
        if (row < mend) {
            float* dst = d_act + (size_t)row * FDIM + n0 + tx * 8;
            #pragma unroll
            for (int jj = 0; jj < 2; jj++) {
                float4 v;
                float g0 = accg[i][jj*4+0], g1 = accg[i][jj*4+1], g2 = accg[i][jj*4+2], g3 = accg[i][jj*4+3];
                v.x = g0 / (1.f + expf(-g0)) * accu[i][jj*4+0];
                v.y = g1 / (1.f + expf(-g1)) * accu[i][jj*4+1];
                v.z = g2 / (1.f + expf(-g2)) * accu[i][jj*4+2];
                v.w = g3 / (1.f + expf(-g3)) * accu[i][jj*4+3];
                *(float4*)(dst + jj * 4) = v;
            }
        }
    }
}

// ---------------- kernel 6: GEMM2  h = (act @ downW^T) * combine_weight ----------------
__global__ void __launch_bounds__(256) gemm2_kernel(const float* __restrict__ dw)
{
    const int tile = blockIdx.y;
    if (tile >= d_ntiles) return;
    const int e = d_tile_e[tile], m0 = d_tile_m0[tile], mend = d_tile_end[tile];
    const int n0 = blockIdx.x * 128;

    const float* B = dw + (size_t)e * DDIM * FDIM;

    __shared__ float As[16][128];
    __shared__ float Bs[16][128];

    const int tid = threadIdx.x;
    const int lrow = tid >> 1;
    const int kq = (tid & 1) * 8;

    int grow = m0 + lrow;
    int arow = grow < NROWS ? grow : (NROWS - 1);
    const float* xrow = d_act + (size_t)arow * FDIM;
    const float* brow = B + (size_t)(n0 + lrow) * FDIM;

    const int tx = tid & 15, ty = tid >> 4;

    float acc[8][8];
    #pragma unroll
    for (int i = 0; i < 8; i++)
        #pragma unroll
        for (int j = 0; j < 8; j++) acc[i][j] = 0.f;

    for (int kc = 0; kc < FDIM; kc += 16) {
        float4 a0 = *(const float4*)(xrow + kc + kq);
        float4 a1 = *(const float4*)(xrow + kc + kq + 4);
        float4 b0 = *(const float4*)(brow + kc + kq);
        float4 b1 = *(const float4*)(brow + kc + kq + 4);
        As[kq + 0][lrow] = a0.x; As[kq + 1][lrow] = a0.y; As[kq + 2][lrow] = a0.z; As[kq + 3][lrow] = a0.w;
        As[kq + 4][lrow] = a1.x; As[kq + 5][lrow] = a1.y; As[kq + 6][lrow] = a1.z; As[kq + 7][lrow] = a1.w;
        Bs[kq + 0][lrow] = b0.x; Bs[kq + 1][lrow] = b0.y; Bs[kq + 2][lrow] = b0.z; Bs[kq + 3][lrow] = b0.w;
        Bs[kq + 4][lrow] = b1.x; Bs[kq + 5][lrow] = b1.y; Bs[kq + 6][lrow] = b1.z; Bs[kq + 7][lrow] = b1.w;
        __syncthreads();
        #pragma unroll
        for (int k = 0; k < 16; k++) {
            float a[8], b[8];
            *(float4*)(a)     = *(const float4*)&As[k][ty * 8];
            *(float4*)(a + 4) = *(const float4*)&As[k][ty * 8 + 4];
            *(float4*)(b)     = *(const float4*)&Bs[k][tx * 8];
            *(float4*)(b + 4) = *(const float4*)&Bs[k][tx * 8 + 4];
            #pragma unroll
            for (int i = 0; i < 8; i++)
                #pragma unroll
                for (int j = 0; j < 8; j++) acc[i][j] += a[i] * b[j];
        }
        __syncthreads();
    }

    #pragma unroll
    for (int i = 0; i < 8; i++) {
        int row = m0 + ty * 8 + i;
        if (row < mend) {
            float wgt = d_row_w[row];
            float* dst = d_hbuf + (size_t)row * DDIM + n0 + tx * 8;
            #pragma unroll
            for (int jj = 0; jj < 2; jj++) {
                float4 v;
                v.x = acc[i][jj*4+0] * wgt; v.y = acc[i][jj*4+1] * wgt;
                v.z = acc[i][jj*4+2] * wgt; v.w = acc[i][jj*4+3] * wgt;
                *(float4*)(dst + jj * 4) = v;
            }
        }
    }
}

// ---------------- kernel 7: combine the two expert contributions per token ----------------
__global__ void combine_kernel(float* __restrict__ out) {
    int gid = blockIdx.x * blockDim.x + threadIdx.x;   // float4 index, T*D/4 total
    int t = gid >> 8;                                  // 256 float4 per token row
    int d4 = gid & 255;
    int r0 = d_token_rows[t * 2 + 0];
    int r1 = d_token_rows[t * 2 + 1];
    float4 h0 = ((const float4*)(d_hbuf + (size_t)r0 * DDIM))[d4];
    float4 h1 = ((const float4*)(d_hbuf + (size_t)r1 * DDIM))[d4];
    float4 v; v.x = h0.x + h1.x; v.y = h0.y + h1.y; v.z = h0.z + h1.z; v.w = h0.w + h1.w;
    ((float4*)(out + (size_t)t * DDIM))[d4] = v;
}

// ---------------- launch ----------------
extern "C" void kernel_launch(void* const* d_in, const int* in_sizes, int n_in,
                              void* d_out, int out_size) {
    const float* x  = (const float*)d_in[0];   // hidden_states [4,2048,1024]
    const float* rw = (const float*)d_in[1];   // router_w [8,1024]
    const float* gw = (const float*)d_in[2];   // gate_w [8,4096,1024]
    const float* uw = (const float*)d_in[3];   // up_w   [8,4096,1024]
    const float* dw = (const float*)d_in[4];   // down_w [8,1024,4096]
    float* out = (float*)d_out;                // [T*D] out, then [T*E] router_logits

    init_kernel<<<1, 32>>>();
    router_kernel<<<T_TOK, 256>>>(x, rw, out);
    offsets_kernel<<<1, 1>>>();
    scatter_kernel<<<T_TOK / 256, 256>>>();
    gemm1_kernel<<<dim3(FDIM / 128, MAXTILES), 256>>>(x, gw, uw);
    gemm2_kernel<<<dim3(DDIM / 128, MAXTILES), 256>>>(dw);
    combine_kernel<<<(T_TOK * DDIM / 4) / 256, 256>>>(out);
}

// round 6
// speedup vs baseline: 3.4354x; 3.4354x over previous
#include <cuda_runtime.h>
#include <cuda_bf16.h>
#include <cstdint>
#include <math.h>

// Problem constants
#define T_TOK 8192
#define DDIM  1024
#define FDIM  4096
#define NE    8
#define TOPK  2
#define NROWS (T_TOK * TOPK)
#define MAXTILES 144
#define KC 32                      // K floats per pipeline chunk
#define ASTR 36                    // smem row stride in floats (36*4=144B, conflict-free)
#define ROWB (ASTR * 4)            // 144 bytes
#define MATB (128 * ROWB)          // 18432 bytes per 128x32 matrix tile
#define G1_STAGE (3 * MATB)        // A + Bg + Bu
#define G2_STAGE (2 * MATB)        // A + B
#define G1_SMEM (3 * G1_STAGE)     // 165888
#define G2_SMEM (3 * G2_STAGE)     // 110592

// ---------------- static device scratch ----------------
__device__ float d_act[(size_t)NROWS * FDIM];
__device__ float d_hbuf[(size_t)NROWS * DDIM];
__device__ int   d_row_token[NROWS];
__device__ float d_row_w[NROWS];
__device__ int   d_token_rows[NROWS];
__device__ int   d_counts[NE];
__device__ int   d_offs[NE];
__device__ int   d_curs[NE];
__device__ int   d_tile_e[MAXTILES];
__device__ int   d_tile_m0[MAXTILES];
__device__ int   d_tile_end[MAXTILES];
__device__ int   d_ntiles;
__device__ int   d_topk_e[NROWS];
__device__ float d_topk_w[NROWS];

// ================= PTX helpers (sm_100 legal subset) =================
__device__ __forceinline__ uint32_t smem_u32(const void* p) {
    uint32_t a;
    asm("{ .reg .u64 t; cvta.to.shared.u64 t, %1; cvt.u32.u64 %0, t; }" : "=r"(a) : "l"(p));
    return a;
}

#define CP_ASYNC(sm, g)  asm volatile("cp.async.cg.shared.global [%0], [%1], 16;" :: "r"(sm), "l"(g) : "memory")
#define CP_COMMIT()      asm volatile("cp.async.commit_group;" ::: "memory")
#define CP_WAIT1()       asm volatile("cp.async.wait_group 1;" ::: "memory")

#define LDSM4(r0, r1, r2, r3, addr) \
    asm volatile("ldmatrix.sync.aligned.m8n8.x4.shared.b16 {%0,%1,%2,%3}, [%4];" \
                 : "=r"(r0), "=r"(r1), "=r"(r2), "=r"(r3) : "r"(addr))

#define CVT_TF32(x) asm("cvt.rna.tf32.f32 %0, %0;" : "+r"(x))

#define MMA8(d, a0, a1, a2, a3, b0, b1) \
    asm volatile("mma.sync.aligned.m16n8k8.row.col.f32.tf32.tf32.f32 " \
                 "{%0,%1,%2,%3}, {%4,%5,%6,%7}, {%8,%9}, {%0,%1,%2,%3};" \
                 : "+f"((d)[0]), "+f"((d)[1]), "+f"((d)[2]), "+f"((d)[3]) \
                 : "r"(a0), "r"(a1), "r"(a2), "r"(a3), "r"(b0), "r"(b1))

// ---------------- kernel 1: zero per-launch state ----------------
__global__ void init_kernel() {
    int i = threadIdx.x;
    if (i < NE) { d_counts[i] = 0; d_curs[i] = 0; }
}

// ---------------- kernel 2: router logits + softmax + top2 ----------------
__global__ void __launch_bounds__(256) router_kernel(
    const float* __restrict__ x, const float* __restrict__ rw, float* __restrict__ out)
{
    __shared__ float xs[DDIM];
    __shared__ float logits[NE];
    const int t = blockIdx.x;
    const int tid = threadIdx.x;

    ((float4*)xs)[tid] = ((const float4*)(x + (size_t)t * DDIM))[tid];
    __syncthreads();

    const int w = tid >> 5, lane = tid & 31;
    const float* r = rw + (size_t)w * DDIM;
    float s = 0.f;
    #pragma unroll 8
    for (int i = lane; i < DDIM; i += 32) s += xs[i] * r[i];
    #pragma unroll
    for (int o = 16; o; o >>= 1) s += __shfl_down_sync(0xffffffffu, s, o);
    if (lane == 0) logits[w] = s;
    __syncthreads();

    if (tid == 0) {
        float l[NE], mx = -1e30f;
        #pragma unroll
        for (int e = 0; e < NE; e++) { l[e] = logits[e]; mx = fmaxf(mx, l[e]); }
        float* lo = out + (size_t)T_TOK * DDIM + (size_t)t * NE;
        #pragma unroll
        for (int e = 0; e < NE; e++) lo[e] = l[e];
        float p[NE], sum = 0.f;
        #pragma unroll
        for (int e = 0; e < NE; e++) { p[e] = expf(l[e] - mx); sum += p[e]; }
        float inv = 1.f / sum;
        #pragma unroll
        for (int e = 0; e < NE; e++) p[e] *= inv;
        int i1 = 0; float p1 = p[0];
        #pragma unroll
        for (int e = 1; e < NE; e++) if (p[e] > p1) { p1 = p[e]; i1 = e; }
        int i2 = -1; float p2 = -1.f;
        #pragma unroll
        for (int e = 0; e < NE; e++) if (e != i1 && p[e] > p2) { p2 = p[e]; i2 = e; }
        d_topk_e[t * 2 + 0] = i1; d_topk_w[t * 2 + 0] = p1;
        d_topk_e[t * 2 + 1] = i2; d_topk_w[t * 2 + 1] = p2;
        atomicAdd(&d_counts[i1], 1);
        atomicAdd(&d_counts[i2], 1);
    }
}

// ---------------- kernel 3: offsets + tile table ----------------
__global__ void offsets_kernel() {
    if (threadIdx.x != 0 || blockIdx.x != 0) return;
    int off = 0;
    for (int e = 0; e < NE; e++) { d_offs[e] = off; off += d_counts[e]; }
    int nt = 0;
    for (int e = 0; e < NE; e++) {
        int start = d_offs[e], cnt = d_counts[e];
        for (int i = 0; i < cnt; i += 128) {
            d_tile_e[nt] = e; d_tile_m0[nt] = start + i; d_tile_end[nt] = start + cnt;
            nt++;
        }
    }
    d_ntiles = nt;
}

// ---------------- kernel 4: scatter ----------------
__global__ void scatter_kernel() {
    int t = blockIdx.x * blockDim.x + threadIdx.x;
    if (t >= T_TOK) return;
    #pragma unroll
    for (int slot = 0; slot < TOPK; slot++) {
        int e = d_topk_e[t * 2 + slot];
        int pos = atomicAdd(&d_curs[e], 1);
        int r = d_offs[e] + pos;
        d_row_token[r] = t;
        d_row_w[r] = d_topk_w[t * 2 + slot];
        d_token_rows[t * 2 + slot] = r;
    }
}

// ================= GEMM1 (mma.sync tf32): act = silu(x@gW^T) * (x@uW^T) =================
// 512 threads. Warps 0-7 compute gate, warps 8-15 compute up (same A in smem).
// Tile M=128 x N=128, K-chunk 32, 3-stage cp.async pipeline.
__global__ void __launch_bounds__(512) gemm1_mma(
    const float* __restrict__ x, const float* __restrict__ gw, const float* __restrict__ uw)
{
    const int tile = blockIdx.y;
    if (tile >= d_ntiles) return;
    const int e = d_tile_e[tile], m0 = d_tile_m0[tile], mend = d_tile_end[tile];
    const int n0 = blockIdx.x * 128;

    extern __shared__ __align__(128) char smem[];
    const uint32_t sb = smem_u32(smem);
    const int tid = threadIdx.x, wid = tid >> 5, lane = tid & 31;

    // ---- per-thread cp.async source/dest (6 x 16B chunks per stage) ----
    const float* gp[6]; uint32_t so[6];
    #pragma unroll
    for (int s = 0; s < 6; s++) {
        int ci = tid + s * 512;
        int mat = ci >> 10;              // 0 = A, 1 = Bg, 2 = Bu
        int f4 = ci & 1023;
        int r = f4 >> 3, c4 = f4 & 7;
        const float* base;
        if (mat == 0) {
            int gr = m0 + r; if (gr > NROWS - 1) gr = NROWS - 1;
            base = x + (size_t)d_row_token[gr] * DDIM;
        } else if (mat == 1) {
            base = gw + (size_t)e * FDIM * DDIM + (size_t)(n0 + r) * DDIM;
        } else {
            base = uw + (size_t)e * FDIM * DDIM + (size_t)(n0 + r) * DDIM;
        }
        gp[s] = base + c4 * 4;
        so[s] = mat * MATB + r * ROWB + c4 * 16;
    }

    // ---- warp tiling: 8 compute warps as 2(M) x 4(N); warps 8-15 mirror for up ----
    const int cwid = wid & 7;
    const int wm = cwid >> 2, wn = cwid & 3;
    const int sel = lane >> 3, rowin = lane & 7;
    const int a_row = (sel & 1) * 8 + rowin;   // + wm*64 + mt*16
    const int a_koff = (sel >> 1) * 4;
    const int b_row = (sel >> 1) * 8 + rowin;  // + wn*32 + p*16
    const int b_koff = (sel & 1) * 4;
    const uint32_t bmat = (wid < 8) ? (uint32_t)MATB : (uint32_t)(2 * MATB);

    float acc[4][4][4];
    #pragma unroll
    for (int i = 0; i < 4; i++)
        #pragma unroll
        for (int j = 0; j < 4; j++)
            #pragma unroll
            for (int q = 0; q < 4; q++) acc[i][j][q] = 0.f;

    auto LOAD = [&](int kc, int buf) {
        const uint32_t sbase = sb + buf * G1_STAGE;
        const int koff = kc * KC;
        #pragma unroll
        for (int s = 0; s < 6; s++) CP_ASYNC(sbase + so[s], gp[s] + koff);
    };

    auto COMPUTE = [&](int buf) {
        const uint32_t abase = sb + buf * G1_STAGE;
        const uint32_t bbase = abase + bmat;
        #pragma unroll
        for (int ks = 0; ks < 4; ks++) {
            uint32_t a[4][4], b[2][4];
            #pragma unroll
            for (int mt = 0; mt < 4; mt++) {
                uint32_t ad = abase + (uint32_t)((wm * 64 + mt * 16 + a_row) * ROWB + (ks * 8 + a_koff) * 4);
                LDSM4(a[mt][0], a[mt][1], a[mt][2], a[mt][3], ad);
            }
            #pragma unroll
            for (int p = 0; p < 2; p++) {
                uint32_t bd = bbase + (uint32_t)((wn * 32 + p * 16 + b_row) * ROWB + (ks * 8 + b_koff) * 4);
                LDSM4(b[p][0], b[p][1], b[p][2], b[p][3], bd);
            }
            #pragma unroll
            for (int mt = 0; mt < 4; mt++)
                #pragma unroll
                for (int q = 0; q < 4; q++) CVT_TF32(a[mt][q]);
            #pragma unroll
            for (int p = 0; p < 2; p++)
                #pragma unroll
                for (int q = 0; q < 4; q++) CVT_TF32(b[p][q]);
            #pragma unroll
            for (int mt = 0; mt < 4; mt++)
                #pragma unroll
                for (int nt = 0; nt < 4; nt++)
                    MMA8(acc[mt][nt], a[mt][0], a[mt][1], a[mt][2], a[mt][3],
                         b[nt >> 1][(nt & 1) * 2], b[nt >> 1][(nt & 1) * 2 + 1]);
        }
    };

    LOAD(0, 0); CP_COMMIT();
    LOAD(1, 1); CP_COMMIT();
    #pragma unroll 1
    for (int kc = 0; kc < DDIM / KC; kc++) {
        CP_WAIT1();
        __syncthreads();
        COMPUTE(kc % 3);
        __syncthreads();
        if (kc + 2 < DDIM / KC) LOAD(kc + 2, (kc + 2) % 3);
        CP_COMMIT();
    }

    // ---- epilogue: up-warps stage u via smem (stride 132 = conflict-free), gate-warps fuse silu ----
    float* ub = (float*)smem;
    const int gid4 = lane >> 2, tg = lane & 3;
    if (wid >= 8) {
        #pragma unroll
        for (int mt = 0; mt < 4; mt++)
            #pragma unroll
            for (int nt = 0; nt < 4; nt++) {
                int r = wm * 64 + mt * 16 + gid4, c = wn * 32 + nt * 8 + 2 * tg;
                ub[r * 132 + c]       = acc[mt][nt][0];
                ub[r * 132 + c + 1]   = acc[mt][nt][1];
                ub[(r + 8) * 132 + c]     = acc[mt][nt][2];
                ub[(r + 8) * 132 + c + 1] = acc[mt][nt][3];
            }
    }
    __syncthreads();
    if (wid < 8) {
        #pragma unroll
        for (int mt = 0; mt < 4; mt++)
            #pragma unroll
            for (int nt = 0; nt < 4; nt++) {
                int r = wm * 64 + mt * 16 + gid4, c = wn * 32 + nt * 8 + 2 * tg;
                #pragma unroll
                for (int h = 0; h < 2; h++) {
                    int rr = r + h * 8;
                    int gr = m0 + rr;
                    if (gr < mend) {
                        float g0 = acc[mt][nt][h * 2], g1 = acc[mt][nt][h * 2 + 1];
                        float u0 = ub[rr * 132 + c], u1 = ub[rr * 132 + c + 1];
                        float2 v;
                        v.x = g0 / (1.f + __expf(-g0)) * u0;
                        v.y = g1 / (1.f + __expf(-g1)) * u1;
                        *(float2*)(d_act + (size_t)gr * FDIM + n0 + c) = v;
                    }
                }
            }
    }
}

// ================= GEMM2 (mma.sync tf32): h = (act @ dW^T) * combine_w =================
// 256 threads, 8 warps as 2(M) x 4(N). K = 4096, 128 chunks.
__global__ void __launch_bounds__(256) gemm2_mma(const float* __restrict__ dw)
{
    const int tile = blockIdx.y;
    if (tile >= d_ntiles) return;
    const int e = d_tile_e[tile], m0 = d_tile_m0[tile], mend = d_tile_end[tile];
    const int n0 = blockIdx.x * 128;

    extern __shared__ __align__(128) char smem[];
    const uint32_t sb = smem_u32(smem);
    const int tid = threadIdx.x, wid = tid >> 5, lane = tid & 31;

    const float* gp[8]; uint32_t so[8];
    #pragma unroll
    for (int s = 0; s < 8; s++) {
        int ci = tid + s * 256;
        int mat = ci >> 10;              // 0 = A (d_act), 1 = B (down_w)
        int f4 = ci & 1023;
        int r = f4 >> 3, c4 = f4 & 7;
        const float* base;
        if (mat == 0) {
            int gr = m0 + r; if (gr > NROWS - 1) gr = NROWS - 1;
            base = d_act + (size_t)gr * FDIM;
        } else {
            base = dw + (size_t)e * DDIM * FDIM + (size_t)(n0 + r) * FDIM;
        }
        gp[s] = base + c4 * 4;
        so[s] = mat * MATB + r * ROWB + c4 * 16;
    }

    const int wm = wid >> 2, wn = wid & 3;
    const int sel = lane >> 3, rowin = lane & 7;
    const int a_row = (sel & 1) * 8 + rowin;
    const int a_koff = (sel >> 1) * 4;
    const int b_row = (sel >> 1) * 8 + rowin;
    const int b_koff = (sel & 1) * 4;

    float acc[4][4][4];
    #pragma unroll
    for (int i = 0; i < 4; i++)
        #pragma unroll
        for (int j = 0; j < 4; j++)
            #pragma unroll
            for (int q = 0; q < 4; q++) acc[i][j][q] = 0.f;

    auto LOAD = [&](int kc, int buf) {
        const uint32_t sbase = sb + buf * G2_STAGE;
        const int koff = kc * KC;
        #pragma unroll
        for (int s = 0; s < 8; s++) CP_ASYNC(sbase + so[s], gp[s] + koff);
    };

    auto COMPUTE = [&](int buf) {
        const uint32_t abase = sb + buf * G2_STAGE;
        const uint32_t bbase = abase + MATB;
        #pragma unroll
        for (int ks = 0; ks < 4; ks++) {
            uint32_t a[4][4], b[2][4];
            #pragma unroll
            for (int mt = 0; mt < 4; mt++) {
                uint32_t ad = abase + (uint32_t)((wm * 64 + mt * 16 + a_row) * ROWB + (ks * 8 + a_koff) * 4);
                LDSM4(a[mt][0], a[mt][1], a[mt][2], a[mt][3], ad);
            }
            #pragma unroll
            for (int p = 0; p < 2; p++) {
                uint32_t bd = bbase + (uint32_t)((wn * 32 + p * 16 + b_row) * ROWB + (ks * 8 + b_koff) * 4);
                LDSM4(b[p][0], b[p][1], b[p][2], b[p][3], bd);
            }
            #pragma unroll
            for (int mt = 0; mt < 4; mt++)
                #pragma unroll
                for (int q = 0; q < 4; q++) CVT_TF32(a[mt][q]);
            #pragma unroll
            for (int p = 0; p < 2; p++)
                #pragma unroll
                for (int q = 0; q < 4; q++) CVT_TF32(b[p][q]);
            #pragma unroll
            for (int mt = 0; mt < 4; mt++)
                #pragma unroll
                for (int nt = 0; nt < 4; nt++)
                    MMA8(acc[mt][nt], a[mt][0], a[mt][1], a[mt][2], a[mt][3],
                         b[nt >> 1][(nt & 1) * 2], b[nt >> 1][(nt & 1) * 2 + 1]);
        }
    };

    LOAD(0, 0); CP_COMMIT();
    LOAD(1, 1); CP_COMMIT();
    #pragma unroll 1
    for (int kc = 0; kc < FDIM / KC; kc++) {
        CP_WAIT1();
        __syncthreads();
        COMPUTE(kc % 3);
        __syncthreads();
        if (kc + 2 < FDIM / KC) LOAD(kc + 2, (kc + 2) % 3);
        CP_COMMIT();
    }

    const int gid4 = lane >> 2, tg = lane & 3;
    #pragma unroll
    for (int mt = 0; mt < 4; mt++)
        #pragma unroll
        for (int nt = 0; nt < 4; nt++) {
            int r = wm * 64 + mt * 16 + gid4, c = wn * 32 + nt * 8 + 2 * tg;
            #pragma unroll
            for (int h = 0; h < 2; h++) {
                int rr = r + h * 8;
                int gr = m0 + rr;
                if (gr < mend) {
                    float wgt = d_row_w[gr];
                    float2 v;
                    v.x = acc[mt][nt][h * 2] * wgt;
                    v.y = acc[mt][nt][h * 2 + 1] * wgt;
                    *(float2*)(d_hbuf + (size_t)gr * DDIM + n0 + c) = v;
                }
            }
        }
}

// ---------------- kernel 7: combine ----------------
__global__ void combine_kernel(float* __restrict__ out) {
    int gid = blockIdx.x * blockDim.x + threadIdx.x;
    int t = gid >> 8;
    int d4 = gid & 255;
    int r0 = d_token_rows[t * 2 + 0];
    int r1 = d_token_rows[t * 2 + 1];
    float4 h0 = ((const float4*)(d_hbuf + (size_t)r0 * DDIM))[d4];
    float4 h1 = ((const float4*)(d_hbuf + (size_t)r1 * DDIM))[d4];
    float4 v; v.x = h0.x + h1.x; v.y = h0.y + h1.y; v.z = h0.z + h1.z; v.w = h0.w + h1.w;
    ((float4*)(out + (size_t)t * DDIM))[d4] = v;
}

// ---------------- launch ----------------
extern "C" void kernel_launch(void* const* d_in, const int* in_sizes, int n_in,
                              void* d_out, int out_size) {
    const float* x  = (const float*)d_in[0];
    const float* rw = (const float*)d_in[1];
    const float* gw = (const float*)d_in[2];
    const float* uw = (const float*)d_in[3];
    const float* dw = (const float*)d_in[4];
    float* out = (float*)d_out;

    cudaFuncSetAttribute(gemm1_mma, cudaFuncAttributeMaxDynamicSharedMemorySize, G1_SMEM);
    cudaFuncSetAttribute(gemm2_mma, cudaFuncAttributeMaxDynamicSharedMemorySize, G2_SMEM);

    init_kernel<<<1, 32>>>();
    router_kernel<<<T_TOK, 256>>>(x, rw, out);
    offsets_kernel<<<1, 1>>>();
    scatter_kernel<<<T_TOK / 256, 256>>>();
    gemm1_mma<<<dim3(FDIM / 128, MAXTILES), 512, G1_SMEM>>>(x, gw, uw);
    gemm2_mma<<<dim3(DDIM / 128, MAXTILES), 256, G2_SMEM>>>(dw);
    combine_kernel<<<(T_TOK * DDIM / 4) / 256, 256>>>(out);
}